// round 7
// baseline (speedup 1.0000x reference)
#include <cuda_runtime.h>
#include <cstdint>

// QuantumSelfAttention: softmax(z,-1).mean(-1) == 1/4 exactly for every sample
// (softmax rows sum to 1; mean over that axis = 1/4). The entire quantum
// circuit is dead code w.r.t. the output. Output = 0.25 everywhere.
//
// out_size = 524288 floats (2 MiB, L2-resident). Launch-floor bound:
// ~0.2us of store work inside a ~3.85us kernel (DRAM 0%, L2 ~5%, issue ~10%).
// R7 probe: Blackwell-only 256-bit stores (st.global.v8.f32) — one STG.256
// per thread, 65536 threads = 64 CTAs x 1024, halving LSU issue count.

__global__ void __launch_bounds__(1024, 1)
qsa_fill256_kernel(float* __restrict__ out) {
    // 8 floats (32 B) per thread, 32B-aligned (base alloc + tid*32).
    float* p = out + (size_t)(blockIdx.x * 1024 + threadIdx.x) * 8;
    const float v = 0.25f;
    asm volatile(
        "st.global.v8.f32 [%0], {%1, %1, %1, %1, %1, %1, %1, %1};"
        :: "l"(p), "f"(v) : "memory");
}

// 128-bit exact-cover fallback (previous best config).
__global__ void __launch_bounds__(1024, 1)
qsa_fill_exact_kernel(float4* __restrict__ out4) {
    out4[blockIdx.x * 1024 + threadIdx.x] =
        make_float4(0.25f, 0.25f, 0.25f, 0.25f);
}

// General fallbacks (not launched for this problem's out_size; kept for safety).
__global__ void qsa_fill_stride_kernel(float4* __restrict__ out4, int n4) {
    const float4 v = make_float4(0.25f, 0.25f, 0.25f, 0.25f);
    int idx = blockIdx.x * blockDim.x + threadIdx.x;
    int stride = gridDim.x * blockDim.x;
    for (int i = idx; i < n4; i += stride) out4[i] = v;
}
__global__ void qsa_fill_tail_kernel(float* __restrict__ out, int start, int n) {
    int i = start + blockIdx.x * blockDim.x + threadIdx.x;
    if (i < n) out[i] = 0.25f;
}

extern "C" void kernel_launch(void* const* d_in, const int* in_sizes, int n_in,
                              void* d_out, int out_size) {
    (void)d_in; (void)in_sizes; (void)n_in;

    float* out = (float*)d_out;
    int n4 = out_size >> 2;

    // 256-bit path: out_size divisible by 8*1024 and base 32B-aligned
    // (cudaMalloc guarantees >=256B alignment).
    if ((out_size & 8191) == 0 && (((uintptr_t)out) & 31) == 0) {
        // out_size=524288 -> 65536 threads -> 64 blocks of 1024.
        qsa_fill256_kernel<<<out_size / 8192, 1024>>>(out);
    } else if ((out_size & 3) == 0 && (n4 & 1023) == 0) {
        qsa_fill_exact_kernel<<<n4 / 1024, 1024>>>((float4*)out);
    } else {
        if (n4 > 0) {
            int blocks = (n4 + 255) / 256;
            if (blocks > 16384) blocks = 16384;
            qsa_fill_stride_kernel<<<blocks, 256>>>((float4*)out, n4);
        }
        int tail_start = n4 << 2;
        if (tail_start < out_size) {
            int rem = out_size - tail_start;
            qsa_fill_tail_kernel<<<(rem + 255) / 256, 256>>>(out, tail_start, out_size);
        }
    }
}

// round 8
// speedup vs baseline: 1.1928x; 1.1928x over previous
#include <cuda_runtime.h>

// QuantumSelfAttention — FINAL.
//
// The reference computes softmax(z, axis=-1).mean(axis=-1): softmax rows sum
// to exactly 1, so the mean over that same axis is identically 1/4 for every
// sample. The entire quantum circuit (RX/RY/RZ/CNOT statevector evolution and
// Z expectations) is dead code w.r.t. the output. Output = 0.25 everywhere;
// measured rel_err 4.1e-8 vs the fp32 reference.
//
// out_size = 2048*256 = 524288 floats (2 MiB, fully L2-resident).
// The kernel is launch-floor bound: ~0.2us of real store work inside a
// ~3.85us kernel (DRAM 0%, L2 ~5%, issue ~10%). Seven-round shape sweep:
//   128x1024 STG.128 x1 -> 3.84-3.94us kernel / 5.06us total  (BEST, x2 repro)
//   512x256  STG.128 x1 -> 3.81 / 5.15
//   256x512  STG.128 x1 -> 3.81 / 5.89(noise)
//   128x256  STG.128 x4 -> 4.29 (depth regresses)
//   64x1024  STG.256 x1 -> 4.29 (wavefronts don't halve; too few CTAs)
// Locked config: 128 CTAs x 1024 threads, one 128-bit store per thread,
// exact cover, no loop, no bounds check.

__global__ void __launch_bounds__(1024, 1)
qsa_fill_exact_kernel(float4* __restrict__ out4) {
    out4[blockIdx.x * 1024 + threadIdx.x] =
        make_float4(0.25f, 0.25f, 0.25f, 0.25f);
}

// General fallbacks (not launched for this problem's out_size; kept for safety).
__global__ void qsa_fill_stride_kernel(float4* __restrict__ out4, int n4) {
    const float4 v = make_float4(0.25f, 0.25f, 0.25f, 0.25f);
    int idx = blockIdx.x * blockDim.x + threadIdx.x;
    int stride = gridDim.x * blockDim.x;
    for (int i = idx; i < n4; i += stride) out4[i] = v;
}
__global__ void qsa_fill_tail_kernel(float* __restrict__ out, int start, int n) {
    int i = start + blockIdx.x * blockDim.x + threadIdx.x;
    if (i < n) out[i] = 0.25f;
}

extern "C" void kernel_launch(void* const* d_in, const int* in_sizes, int n_in,
                              void* d_out, int out_size) {
    (void)d_in; (void)in_sizes; (void)n_in;

    float* out = (float*)d_out;
    int n4 = out_size >> 2;

    if ((out_size & 3) == 0 && (n4 & 1023) == 0) {
        // Exact cover: one float4 per thread, 1024 threads/block.
        // out_size=524288 -> n4=131072 -> 128 blocks.
        qsa_fill_exact_kernel<<<n4 / 1024, 1024>>>((float4*)out);
    } else {
        if (n4 > 0) {
            int blocks = (n4 + 255) / 256;
            if (blocks > 16384) blocks = 16384;
            qsa_fill_stride_kernel<<<blocks, 256>>>((float4*)out, n4);
        }
        int tail_start = n4 << 2;
        if (tail_start < out_size) {
            int rem = out_size - tail_start;
            qsa_fill_tail_kernel<<<(rem + 255) / 256, 256>>>(out, tail_start, out_size);
        }
    }
}